// round 11
// baseline (speedup 1.0000x reference)
#include <cuda_runtime.h>
#include <cuda_fp16.h>
#include <cstdint>

#define D_IN   4096
#define D_OUT  4096
#define NROWS  8192
#define RANK   16

// ---------------- scratch ----------------
__device__ __align__(1024) __half g_Wh[D_OUT * D_IN];  // W^T [N][K], fp16
__device__ __align__(1024) __half g_Xh[NROWS * D_IN];  // X, fp16
__device__ __align__(16)   float  g_T [NROWS * RANK];  // X @ L1 (fp32)
#define KSPLIT 8
__device__ __align__(16)   float  g_Tp[KSPLIT * NROWS * RANK]; // partials

// ---------------- helpers ----------------
__device__ __forceinline__ uint32_t smem_u32(const void* p) {
    return (uint32_t)__cvta_generic_to_shared(p);
}
#define CP_ASYNC16(dst, src) \
    asm volatile("cp.async.cg.shared.global [%0], [%1], 16;\n" :: "r"(dst), "l"(src))
#define CP_COMMIT  asm volatile("cp.async.commit_group;\n" ::: "memory")
#define CP_WAIT1   asm volatile("cp.async.wait_group 1;\n" ::: "memory")

#define LDSM_X4(r0, r1, r2, r3, a) \
    asm volatile("ldmatrix.sync.aligned.m8n8.x4.shared.b16 {%0,%1,%2,%3}, [%4];" \
        : "=r"(r0), "=r"(r1), "=r"(r2), "=r"(r3) : "r"(a))

__device__ __forceinline__ void mma_16816(float* c, const uint32_t* a, const uint32_t* b) {
    asm volatile(
        "mma.sync.aligned.m16n8k16.row.col.f32.f16.f16.f32 "
        "{%0,%1,%2,%3}, {%4,%5,%6,%7}, {%8,%9}, {%0,%1,%2,%3};\n"
        : "+f"(c[0]), "+f"(c[1]), "+f"(c[2]), "+f"(c[3])
        : "r"(a[0]), "r"(a[1]), "r"(a[2]), "r"(a[3]), "r"(b[0]), "r"(b[1]));
}

// ============================================================
// Kernel 1: dequant + transpose to fp16: g_Wh[n][k] = h(W[k][n]*c1*ck[k][n])
// ============================================================
__global__ void dequant_t_kernel(const float* __restrict__ w,
                                 const float* __restrict__ c1p,
                                 const float* __restrict__ ck) {
    __shared__ float tile[32][33];
    const float c1 = c1p[0];
    const int n0 = blockIdx.x * 32, k0 = blockIdx.y * 32;
    const int tx = threadIdx.x, ty = threadIdx.y;   // (32, 8)
    #pragma unroll
    for (int i = 0; i < 4; i++) {
        int k = k0 + ty + i * 8;
        size_t idx = (size_t)k * D_OUT + n0 + tx;
        tile[ty + i * 8][tx] = (w[idx] * c1) * ck[idx];
    }
    __syncthreads();
    #pragma unroll
    for (int i = 0; i < 4; i++) {
        int n = n0 + ty + i * 8;
        g_Wh[(size_t)n * D_IN + k0 + tx] = __float2half_rn(tile[tx][ty + i * 8]);
    }
}

// ============================================================
// Kernel 2: retiled T-partial = X @ L1 (+ fused fp16(X) conversion)
// ============================================================
#define KCHUNK (D_IN / KSPLIT)   // 512
#define XTK 32
#define XROWS 256

__global__ __launch_bounds__(256)
void xl1_kernel(const float* __restrict__ X, const float* __restrict__ L1) {
    __shared__ float xs[XROWS * 33];
    __shared__ __align__(16) float l1s[XTK][RANK];
    const int tid  = threadIdx.x;
    const int ks   = blockIdx.x;
    const int row0 = blockIdx.y * XROWS;
    const int k0   = ks * KCHUNK;

    float acc[RANK];
    #pragma unroll
    for (int r = 0; r < RANK; r++) acc[r] = 0.f;

    for (int t = 0; t < KCHUNK / XTK; t++) {
        const int kt = k0 + t * XTK;
        __syncthreads();
        #pragma unroll
        for (int j = 0; j < 8; j++) {
            int f = tid + j * 256;
            int row = f >> 3, seg = f & 7;
            float4 v = *(const float4*)(X + (size_t)(row0 + row) * D_IN + kt + seg * 4);
            float* xd = xs + row * 33 + seg * 4;
            xd[0] = v.x; xd[1] = v.y; xd[2] = v.z; xd[3] = v.w;
            __half2 h0 = __floats2half2_rn(v.x, v.y);
            __half2 h1 = __floats2half2_rn(v.z, v.w);
            uint2 u = make_uint2(*(uint32_t*)&h0, *(uint32_t*)&h1);
            *(uint2*)(g_Xh + (size_t)(row0 + row) * D_IN + kt + seg * 4) = u;
        }
        if (tid < 128) {
            int kk = tid >> 2, rq = tid & 3;
            *(float4*)&l1s[kk][rq * 4] =
                *(const float4*)(L1 + (size_t)(kt + kk) * RANK + rq * 4);
        }
        __syncthreads();
        const float* xr = xs + tid * 33;
        #pragma unroll
        for (int kk = 0; kk < XTK; kk++) {
            float x = xr[kk];
            float4 a = *(const float4*)&l1s[kk][0];
            float4 b = *(const float4*)&l1s[kk][4];
            float4 c = *(const float4*)&l1s[kk][8];
            float4 d = *(const float4*)&l1s[kk][12];
            acc[0]  += x * a.x; acc[1]  += x * a.y; acc[2]  += x * a.z; acc[3]  += x * a.w;
            acc[4]  += x * b.x; acc[5]  += x * b.y; acc[6]  += x * b.z; acc[7]  += x * b.w;
            acc[8]  += x * c.x; acc[9]  += x * c.y; acc[10] += x * c.z; acc[11] += x * c.w;
            acc[12] += x * d.x; acc[13] += x * d.y; acc[14] += x * d.z; acc[15] += x * d.w;
        }
    }
    float* out = g_Tp + ((size_t)ks * NROWS + row0 + tid) * RANK;
    #pragma unroll
    for (int q = 0; q < 4; q++)
        *(float4*)(out + q * 4) = make_float4(acc[q * 4], acc[q * 4 + 1],
                                              acc[q * 4 + 2], acc[q * 4 + 3]);
}

// ============================================================
// Kernel 2b: g_T = sum over k-split partials
// ============================================================
__global__ void treduce_kernel() {
    const int i = (blockIdx.x * 256 + threadIdx.x) * 4;
    float4 s = make_float4(0.f, 0.f, 0.f, 0.f);
    #pragma unroll
    for (int ks = 0; ks < KSPLIT; ks++) {
        float4 v = *(const float4*)(g_Tp + (size_t)ks * NROWS * RANK + i);
        s.x += v.x; s.y += v.y; s.z += v.z; s.w += v.w;
    }
    *(float4*)(g_T + i) = s;
}

// ============================================================
// Kernel 3: fp16 mma.sync GEMM, BM=128 BN=128 BK=64,
//           3-stage cp.async, 2 CTAs/SM, fused LoRA epilogue
// ============================================================
#define BM 128
#define BN 128
#define BK 64
#define KTILES (D_IN / BK)           // 64
#define A_BYTES (BM * BK * 2)        // 16384
#define B_BYTES (BN * BK * 2)        // 16384
#define STAGE_BYTES (A_BYTES + B_BYTES)  // 32768
#define STAGES 3
#define SMEM_L2  (STAGES * STAGE_BYTES)      // 98304
#define SMEM_TS  (SMEM_L2 + RANK * BN * 4)   // +8192
#define SMEM_TOT (SMEM_TS + BM * RANK * 4)   // +8192 = 114688

__global__ __launch_bounds__(256, 2)
void gemm_hmma_kernel(float* __restrict__ Y, const float* __restrict__ L2) {
    extern __shared__ __align__(1024) unsigned char smem[];
    const uint32_t sbase = smem_u32(smem);
    const int tid = threadIdx.x, warp = tid >> 5, lane = tid & 31;
    const int bN = blockIdx.x, bM = blockIdx.y;
    const int wm = warp & 1, wn = warp >> 1;       // 2 x 4 warps, 64x32 tiles
    const int li = lane & 7, sel = lane >> 3;

    const __half* Ag = g_Xh + (size_t)(bM * BM) * D_IN;
    const __half* Bg = g_Wh + (size_t)(bN * BN) * D_IN;

    auto load_stage = [&](int buf, int kt) {
        const uint32_t ab = sbase + buf * STAGE_BYTES;
        const uint32_t bb = ab + A_BYTES;
        #pragma unroll
        for (int j = 0; j < 4; j++) {          // A: 128 rows x 8 chunks
            int id = tid + j * 256, r = id >> 3, c = id & 7;
            CP_ASYNC16(ab + r * 128 + (((c ^ (r & 7))) << 4),
                       Ag + (size_t)r * D_IN + kt * BK + c * 8);
        }
        #pragma unroll
        for (int j = 0; j < 4; j++) {          // B: 128 rows x 8 chunks
            int id = tid + j * 256, r = id >> 3, c = id & 7;
            CP_ASYNC16(bb + r * 128 + (((c ^ (r & 7))) << 4),
                       Bg + (size_t)r * D_IN + kt * BK + c * 8);
        }
        CP_COMMIT;
    };

    load_stage(0, 0);
    load_stage(1, 1);

    float* l2s = (float*)(smem + SMEM_L2);     // [RANK][BN]
    float* ts  = (float*)(smem + SMEM_TS);     // [BM][RANK]
    #pragma unroll
    for (int j = 0; j < 2; j++) {              // 16*128 floats = 512 float4
        int idx = tid + j * 256, r = idx >> 5, c4 = idx & 31;
        *(float4*)&l2s[r * BN + c4 * 4] =
            *(const float4*)&L2[(size_t)r * D_OUT + bN * BN + c4 * 4];
    }
    #pragma unroll
    for (int j = 0; j < 2; j++) {              // 128*16 floats = 512 float4
        int idx = tid + j * 256, r = idx >> 2, c4 = idx & 3;
        *(float4*)&ts[r * RANK + c4 * 4] =
            *(const float4*)&g_T[(size_t)(bM * BM + r) * RANK + c4 * 4];
    }

    float c[4][4][4];
    #pragma unroll
    for (int mt = 0; mt < 4; mt++)
        #pragma unroll
        for (int nt = 0; nt < 4; nt++)
            #pragma unroll
            for (int i = 0; i < 4; i++) c[mt][nt][i] = 0.f;

    const int a_selr = sel & 1, a_selc = sel >> 1;
    const int b_selr = sel >> 1, b_selc = sel & 1;

    for (int kt = 0; kt < KTILES; ++kt) {
        CP_WAIT1;                              // stage kt resident
        __syncthreads();                       // also guards buffer (kt+2)%3 reuse
        if (kt + 2 < KTILES) load_stage((kt + 2) % 3, kt + 2);
        else                 CP_COMMIT;

        const uint32_t ab = sbase + (kt % 3) * STAGE_BYTES;
        const uint32_t bb = ab + A_BYTES;

        #pragma unroll
        for (int ks = 0; ks < 4; ks++) {
            const int c0 = ks * 2;
            uint32_t a[4][4], b[4][2];
            #pragma unroll
            for (int mt = 0; mt < 4; mt++) {
                int row = wm * 64 + mt * 16 + li + a_selr * 8;
                int ch  = c0 + a_selc;
                LDSM_X4(a[mt][0], a[mt][1], a[mt][2], a[mt][3],
                        ab + row * 128 + (((ch ^ (row & 7))) << 4));
            }
            #pragma unroll
            for (int p = 0; p < 2; p++) {
                int row = wn * 32 + p * 16 + li + b_selr * 8;
                int ch  = c0 + b_selc;
                LDSM_X4(b[p * 2][0], b[p * 2][1], b[p * 2 + 1][0], b[p * 2 + 1][1],
                        bb + row * 128 + (((ch ^ (row & 7))) << 4));
            }
            #pragma unroll
            for (int mt = 0; mt < 4; mt++)
                #pragma unroll
                for (int nt = 0; nt < 4; nt++)
                    mma_16816(c[mt][nt], a[mt], b[nt]);
        }
    }

    // ---------- epilogue: Y = C + T @ L2 ----------
    const int r0 = lane >> 2, cp = (lane & 3) * 2;
    #pragma unroll
    for (int mt = 0; mt < 4; mt++) {
        const int lrA = wm * 64 + mt * 16 + r0;
        const int lrB = lrA + 8;
        float tA[RANK], tB[RANK];
        #pragma unroll
        for (int r = 0; r < RANK; r++) {
            tA[r] = ts[lrA * RANK + r];
            tB[r] = ts[lrB * RANK + r];
        }
        float* yA = Y + (size_t)(bM * BM + lrA) * D_OUT + bN * BN;
        float* yB = Y + (size_t)(bM * BM + lrB) * D_OUT + bN * BN;
        #pragma unroll
        for (int nt = 0; nt < 4; nt++) {
            const int col = wn * 32 + nt * 8 + cp;
            float2 aacc = make_float2(c[mt][nt][0], c[mt][nt][1]);
            float2 bacc = make_float2(c[mt][nt][2], c[mt][nt][3]);
            #pragma unroll
            for (int r = 0; r < RANK; r++) {
                float2 l = *(const float2*)&l2s[r * BN + col];
                aacc.x += tA[r] * l.x; aacc.y += tA[r] * l.y;
                bacc.x += tB[r] * l.x; bacc.y += tB[r] * l.y;
            }
            __stcs((float2*)(yA + col), aacc);
            __stcs((float2*)(yB + col), bacc);
        }
    }
}

// ============================================================
// launch
// ============================================================
extern "C" void kernel_launch(void* const* d_in, const int* in_sizes, int n_in,
                              void* d_out, int out_size) {
    const float* X  = (const float*)d_in[0];
    const float* Wn = (const float*)d_in[1];
    const float* c1 = (const float*)d_in[2];
    const float* ck = (const float*)d_in[3];
    const float* L1 = (const float*)d_in[4];
    const float* L2 = (const float*)d_in[5];
    float* Y = (float*)d_out;

    cudaFuncSetAttribute(gemm_hmma_kernel,
                         cudaFuncAttributeMaxDynamicSharedMemorySize, SMEM_TOT);

    dequant_t_kernel<<<dim3(D_OUT / 32, D_IN / 32), dim3(32, 8)>>>(Wn, c1, ck);
    xl1_kernel<<<dim3(KSPLIT, NROWS / XROWS), 256>>>(X, L1);
    treduce_kernel<<<(NROWS * RANK / 4) / 256, 256>>>();
    gemm_hmma_kernel<<<dim3(D_OUT / BN, NROWS / BM), 256, SMEM_TOT>>>(Y, L2);
}

// round 13
// speedup vs baseline: 1.0374x; 1.0374x over previous
#include <cuda_runtime.h>
#include <cuda_fp16.h>
#include <cstdint>

#define D_IN   4096
#define D_OUT  4096
#define NROWS  8192
#define RANK   16

// ---------------- scratch ----------------
__device__ __align__(1024) __half g_Wh[D_OUT * D_IN];  // W^T [N][K], fp16
__device__ __align__(1024) __half g_Xh[NROWS * D_IN];  // X, fp16
#define KSPLIT 8
__device__ __align__(16)   float  g_Tp[KSPLIT * NROWS * RANK]; // X@L1 partials

// ---------------- helpers ----------------
__device__ __forceinline__ uint32_t smem_u32(const void* p) {
    return (uint32_t)__cvta_generic_to_shared(p);
}
#define CP_ASYNC16(dst, src) \
    asm volatile("cp.async.cg.shared.global [%0], [%1], 16;\n" :: "r"(dst), "l"(src))

__device__ __forceinline__ void mbar_init(uint32_t a, uint32_t cnt) {
    asm volatile("mbarrier.init.shared.b64 [%0], %1;" :: "r"(a), "r"(cnt) : "memory");
}
__device__ __forceinline__ void mbar_arrive(uint32_t a) {
    asm volatile("mbarrier.arrive.shared.b64 _, [%0];" :: "r"(a) : "memory");
}
// .noinc: completion counts against the init count (default form nets to zero!)
__device__ __forceinline__ void cp_async_arrive_noinc(uint32_t a) {
    asm volatile("cp.async.mbarrier.arrive.noinc.shared.b64 [%0];" :: "r"(a) : "memory");
}
__device__ __forceinline__ void mbar_wait(uint32_t a, uint32_t parity) {
    asm volatile(
        "{\n\t.reg .pred P;\n\t"
        "W%=:\n\t"
        "mbarrier.try_wait.parity.acquire.cta.shared::cta.b64 P, [%0], %1, 0x989680;\n\t"
        "@P bra D%=;\n\t"
        "bra W%=;\n\t"
        "D%=:\n\t}"
        :: "r"(a), "r"(parity) : "memory");
}

#define LDSM_X4(r0, r1, r2, r3, a) \
    asm volatile("ldmatrix.sync.aligned.m8n8.x4.shared.b16 {%0,%1,%2,%3}, [%4];" \
        : "=r"(r0), "=r"(r1), "=r"(r2), "=r"(r3) : "r"(a))

__device__ __forceinline__ void mma_16816(float* c, const uint32_t* a, const uint32_t* b) {
    asm volatile(
        "mma.sync.aligned.m16n8k16.row.col.f32.f16.f16.f32 "
        "{%0,%1,%2,%3}, {%4,%5,%6,%7}, {%8,%9}, {%0,%1,%2,%3};\n"
        : "+f"(c[0]), "+f"(c[1]), "+f"(c[2]), "+f"(c[3])
        : "r"(a[0]), "r"(a[1]), "r"(a[2]), "r"(a[3]), "r"(b[0]), "r"(b[1]));
}

// ============================================================
// Kernel 1: dequant + transpose to fp16
// ============================================================
__global__ void dequant_t_kernel(const float* __restrict__ w,
                                 const float* __restrict__ c1p,
                                 const float* __restrict__ ck) {
    __shared__ float tile[32][33];
    const float c1 = c1p[0];
    const int n0 = blockIdx.x * 32, k0 = blockIdx.y * 32;
    const int tx = threadIdx.x, ty = threadIdx.y;
    #pragma unroll
    for (int i = 0; i < 4; i++) {
        int k = k0 + ty + i * 8;
        size_t idx = (size_t)k * D_OUT + n0 + tx;
        tile[ty + i * 8][tx] = (w[idx] * c1) * ck[idx];
    }
    __syncthreads();
    #pragma unroll
    for (int i = 0; i < 4; i++) {
        int n = n0 + ty + i * 8;
        g_Wh[(size_t)n * D_IN + k0 + tx] = __float2half_rn(tile[tx][ty + i * 8]);
    }
}

// ============================================================
// Kernel 2: retiled T-partial = X @ L1 (+ fused fp16(X) conversion)
// ============================================================
#define KCHUNK (D_IN / KSPLIT)   // 512
#define XTK 32
#define XROWS 256

__global__ __launch_bounds__(256)
void xl1_kernel(const float* __restrict__ X, const float* __restrict__ L1) {
    __shared__ float xs[XROWS * 33];
    __shared__ __align__(16) float l1s[XTK][RANK];
    const int tid  = threadIdx.x;
    const int ks   = blockIdx.x;
    const int row0 = blockIdx.y * XROWS;
    const int k0   = ks * KCHUNK;

    float acc[RANK];
    #pragma unroll
    for (int r = 0; r < RANK; r++) acc[r] = 0.f;

    for (int t = 0; t < KCHUNK / XTK; t++) {
        const int kt = k0 + t * XTK;
        __syncthreads();
        #pragma unroll
        for (int j = 0; j < 8; j++) {
            int f = tid + j * 256;
            int row = f >> 3, seg = f & 7;
            float4 v = *(const float4*)(X + (size_t)(row0 + row) * D_IN + kt + seg * 4);
            float* xd = xs + row * 33 + seg * 4;
            xd[0] = v.x; xd[1] = v.y; xd[2] = v.z; xd[3] = v.w;
            __half2 h0 = __floats2half2_rn(v.x, v.y);
            __half2 h1 = __floats2half2_rn(v.z, v.w);
            uint2 u = make_uint2(*(uint32_t*)&h0, *(uint32_t*)&h1);
            *(uint2*)(g_Xh + (size_t)(row0 + row) * D_IN + kt + seg * 4) = u;
        }
        if (tid < 128) {
            int kk = tid >> 2, rq = tid & 3;
            *(float4*)&l1s[kk][rq * 4] =
                *(const float4*)(L1 + (size_t)(kt + kk) * RANK + rq * 4);
        }
        __syncthreads();
        const float* xr = xs + tid * 33;
        #pragma unroll
        for (int kk = 0; kk < XTK; kk++) {
            float x = xr[kk];
            float4 a = *(const float4*)&l1s[kk][0];
            float4 b = *(const float4*)&l1s[kk][4];
            float4 c = *(const float4*)&l1s[kk][8];
            float4 d = *(const float4*)&l1s[kk][12];
            acc[0]  += x * a.x; acc[1]  += x * a.y; acc[2]  += x * a.z; acc[3]  += x * a.w;
            acc[4]  += x * b.x; acc[5]  += x * b.y; acc[6]  += x * b.z; acc[7]  += x * b.w;
            acc[8]  += x * c.x; acc[9]  += x * c.y; acc[10] += x * c.z; acc[11] += x * c.w;
            acc[12] += x * d.x; acc[13] += x * d.y; acc[14] += x * d.z; acc[15] += x * d.w;
        }
    }
    float* out = g_Tp + ((size_t)ks * NROWS + row0 + tid) * RANK;
    #pragma unroll
    for (int q = 0; q < 4; q++)
        *(float4*)(out + q * 4) = make_float4(acc[q * 4], acc[q * 4 + 1],
                                              acc[q * 4 + 2], acc[q * 4 + 3]);
}

// ============================================================
// Kernel 3: fp16 mma.sync GEMM, BM=128 BN=128 BK=64,
//           3-stage mbarrier pipeline (no mainloop __syncthreads),
//           2 CTAs/SM, fused T-reduce + LoRA epilogue
// ============================================================
#define BM 128
#define BN 128
#define BK 64
#define KTILES (D_IN / BK)               // 64
#define A_BYTES (BM * BK * 2)            // 16384
#define B_BYTES (BN * BK * 2)            // 16384
#define STAGE_BYTES (A_BYTES + B_BYTES)  // 32768
#define STAGES 3
#define SMEM_L2   (STAGES * STAGE_BYTES)      // 98304
#define SMEM_TS   (SMEM_L2 + RANK * BN * 4)   // +8192 = 106496
#define SMEM_MBAR (SMEM_TS + BM * RANK * 4)   // +8192 = 114688
#define SMEM_TOT  (SMEM_MBAR + 64)

__global__ __launch_bounds__(256, 2)
void gemm_hmma_kernel(float* __restrict__ Y, const float* __restrict__ L2) {
    extern __shared__ __align__(1024) unsigned char smem[];
    const uint32_t sbase = smem_u32(smem);
    const uint32_t mb_full  = sbase + SMEM_MBAR;        // 3 x 8B
    const uint32_t mb_empty = sbase + SMEM_MBAR + 24;   // 3 x 8B
    const int tid = threadIdx.x, warp = tid >> 5, lane = tid & 31;
    const int bN = blockIdx.x, bM = blockIdx.y;
    const int wm = warp & 1, wn = warp >> 1;       // 2 x 4 warps, 64x32 tiles
    const int li = lane & 7, sel = lane >> 3;

    if (tid == 0) {
        #pragma unroll
        for (int s = 0; s < STAGES; s++) {
            mbar_init(mb_full  + s * 8, 256);   // 256 .noinc cp.async completions
            mbar_init(mb_empty + s * 8, 256);   // 256 thread arrivals
        }
    }
    __syncthreads();   // mbarriers visible before any cp.async targets them

    const __half* Ag = g_Xh + (size_t)(bM * BM) * D_IN;
    const __half* Bg = g_Wh + (size_t)(bN * BN) * D_IN;

    auto load_stage = [&](int buf, int kt) {
        const uint32_t ab = sbase + buf * STAGE_BYTES;
        const uint32_t bb = ab + A_BYTES;
        #pragma unroll
        for (int j = 0; j < 4; j++) {          // A: 128 rows x 8 chunks
            int id = tid + j * 256, r = id >> 3, c = id & 7;
            CP_ASYNC16(ab + r * 128 + (((c ^ (r & 7))) << 4),
                       Ag + (size_t)r * D_IN + kt * BK + c * 8);
        }
        #pragma unroll
        for (int j = 0; j < 4; j++) {          // B: 128 rows x 8 chunks
            int id = tid + j * 256, r = id >> 3, c = id & 7;
            CP_ASYNC16(bb + r * 128 + (((c ^ (r & 7))) << 4),
                       Bg + (size_t)r * D_IN + kt * BK + c * 8);
        }
        cp_async_arrive_noinc(mb_full + buf * 8);
    };

    // prologue: stages 0 and 1
    load_stage(0, 0);
    load_stage(1, 1);

    // LoRA operand tiles; ts = sum of KSPLIT partials (treduce fused here)
    float* l2s = (float*)(smem + SMEM_L2);     // [RANK][BN]
    float* ts  = (float*)(smem + SMEM_TS);     // [BM][RANK]
    #pragma unroll
    for (int j = 0; j < 2; j++) {
        int idx = tid + j * 256, r = idx >> 5, c4 = idx & 31;
        *(float4*)&l2s[r * BN + c4 * 4] =
            *(const float4*)&L2[(size_t)r * D_OUT + bN * BN + c4 * 4];
    }
    #pragma unroll
    for (int j = 0; j < 2; j++) {
        int idx = tid + j * 256, r = idx >> 2, c4 = idx & 3;
        float4 s = make_float4(0.f, 0.f, 0.f, 0.f);
        #pragma unroll
        for (int ks = 0; ks < KSPLIT; ks++) {
            float4 v = *(const float4*)&g_Tp[(size_t)ks * NROWS * RANK +
                                             (size_t)(bM * BM + r) * RANK + c4 * 4];
            s.x += v.x; s.y += v.y; s.z += v.z; s.w += v.w;
        }
        *(float4*)&ts[r * RANK + c4 * 4] = s;
    }
    __syncthreads();   // ts/l2s ready for epilogue (once, cheap)

    float c[4][4][4];
    #pragma unroll
    for (int mt = 0; mt < 4; mt++)
        #pragma unroll
        for (int nt = 0; nt < 4; nt++)
            #pragma unroll
            for (int i = 0; i < 4; i++) c[mt][nt][i] = 0.f;

    const int a_selr = sel & 1, a_selc = sel >> 1;
    const int b_selr = sel >> 1, b_selc = sel & 1;

    for (int kt = 0; kt < KTILES; ++kt) {
        // produce tile kt+2 into stage (kt+2)%3
        const int tp = kt + 2;
        if (tp < KTILES) {
            const int p = tp % 3;
            if (kt > 0)                                  // tp>=3: stage being reused
                mbar_wait(mb_empty + p * 8, ((tp / 3) - 1) & 1);
            load_stage(p, tp);
        }

        // consume tile kt from stage kt%3
        const int s = kt % 3;
        mbar_wait(mb_full + s * 8, (kt / 3) & 1);

        const uint32_t ab = sbase + s * STAGE_BYTES;
        const uint32_t bb = ab + A_BYTES;

        #pragma unroll
        for (int ks = 0; ks < 4; ks++) {
            const int c0 = ks * 2;
            uint32_t a[4][4], b[4][2];
            #pragma unroll
            for (int mt = 0; mt < 4; mt++) {
                int row = wm * 64 + mt * 16 + li + a_selr * 8;
                int ch  = c0 + a_selc;
                LDSM_X4(a[mt][0], a[mt][1], a[mt][2], a[mt][3],
                        ab + row * 128 + (((ch ^ (row & 7))) << 4));
            }
            #pragma unroll
            for (int p = 0; p < 2; p++) {
                int row = wn * 32 + p * 16 + li + b_selr * 8;
                int ch  = c0 + b_selc;
                LDSM_X4(b[p * 2][0], b[p * 2][1], b[p * 2 + 1][0], b[p * 2 + 1][1],
                        bb + row * 128 + (((ch ^ (row & 7))) << 4));
            }
            #pragma unroll
            for (int mt = 0; mt < 4; mt++)
                #pragma unroll
                for (int nt = 0; nt < 4; nt++)
                    mma_16816(c[mt][nt], a[mt], b[nt]);
        }
        mbar_arrive(mb_empty + s * 8);         // this thread done with stage s
    }

    // ---------- epilogue: Y = C + T @ L2 ----------
    const int r0 = lane >> 2, cp = (lane & 3) * 2;
    #pragma unroll
    for (int mt = 0; mt < 4; mt++) {
        const int lrA = wm * 64 + mt * 16 + r0;
        const int lrB = lrA + 8;
        float tA[RANK], tB[RANK];
        #pragma unroll
        for (int r = 0; r < RANK; r++) {
            tA[r] = ts[lrA * RANK + r];
            tB[r] = ts[lrB * RANK + r];
        }
        float* yA = Y + (size_t)(bM * BM + lrA) * D_OUT + bN * BN;
        float* yB = Y + (size_t)(bM * BM + lrB) * D_OUT + bN * BN;
        #pragma unroll
        for (int nt = 0; nt < 4; nt++) {
            const int col = wn * 32 + nt * 8 + cp;
            float2 aacc = make_float2(c[mt][nt][0], c[mt][nt][1]);
            float2 bacc = make_float2(c[mt][nt][2], c[mt][nt][3]);
            #pragma unroll
            for (int r = 0; r < RANK; r++) {
                float2 l = *(const float2*)&l2s[r * BN + col];
                aacc.x += tA[r] * l.x; aacc.y += tA[r] * l.y;
                bacc.x += tB[r] * l.x; bacc.y += tB[r] * l.y;
            }
            __stcs((float2*)(yA + col), aacc);
            __stcs((float2*)(yB + col), bacc);
        }
    }
}

// ============================================================
// launch
// ============================================================
extern "C" void kernel_launch(void* const* d_in, const int* in_sizes, int n_in,
                              void* d_out, int out_size) {
    const float* X  = (const float*)d_in[0];
    const float* Wn = (const float*)d_in[1];
    const float* c1 = (const float*)d_in[2];
    const float* ck = (const float*)d_in[3];
    const float* L1 = (const float*)d_in[4];
    const float* L2 = (const float*)d_in[5];
    float* Y = (float*)d_out;

    cudaFuncSetAttribute(gemm_hmma_kernel,
                         cudaFuncAttributeMaxDynamicSharedMemorySize, SMEM_TOT);

    dequant_t_kernel<<<dim3(D_OUT / 32, D_IN / 32), dim3(32, 8)>>>(Wn, c1, ck);
    xl1_kernel<<<dim3(KSPLIT, NROWS / XROWS), 256>>>(X, L1);
    gemm_hmma_kernel<<<dim3(D_OUT / BN, NROWS / BM), 256, SMEM_TOT>>>(Y, L2);
}

// round 14
// speedup vs baseline: 1.1338x; 1.0929x over previous
#include <cuda_runtime.h>
#include <cuda_fp16.h>
#include <cstdint>

#define D_IN   4096
#define D_OUT  4096
#define NROWS  8192
#define RANK   16

// ---------------- scratch ----------------
__device__ __align__(1024) __half g_Wh[D_OUT * D_IN];  // W^T [N][K], fp16
__device__ __align__(1024) __half g_Xh[NROWS * D_IN];  // X, fp16
#define KSPLIT 8
__device__ __align__(16)   float  g_Tp[KSPLIT * NROWS * RANK]; // X@L1 partials

// ---------------- helpers ----------------
__device__ __forceinline__ uint32_t smem_u32(const void* p) {
    return (uint32_t)__cvta_generic_to_shared(p);
}
#define CP_ASYNC16(dst, src) \
    asm volatile("cp.async.cg.shared.global [%0], [%1], 16;\n" :: "r"(dst), "l"(src))

__device__ __forceinline__ void mbar_init(uint32_t a, uint32_t cnt) {
    asm volatile("mbarrier.init.shared.b64 [%0], %1;" :: "r"(a), "r"(cnt) : "memory");
}
__device__ __forceinline__ void mbar_arrive(uint32_t a) {
    asm volatile("mbarrier.arrive.shared.b64 _, [%0];" :: "r"(a) : "memory");
}
__device__ __forceinline__ void cp_async_arrive_noinc(uint32_t a) {
    asm volatile("cp.async.mbarrier.arrive.noinc.shared.b64 [%0];" :: "r"(a) : "memory");
}
__device__ __forceinline__ void mbar_wait(uint32_t a, uint32_t parity) {
    asm volatile(
        "{\n\t.reg .pred P;\n\t"
        "W%=:\n\t"
        "mbarrier.try_wait.parity.acquire.cta.shared::cta.b64 P, [%0], %1, 0x989680;\n\t"
        "@P bra D%=;\n\t"
        "bra W%=;\n\t"
        "D%=:\n\t}"
        :: "r"(a), "r"(parity) : "memory");
}

#define LDSM_X4(r0, r1, r2, r3, a) \
    asm volatile("ldmatrix.sync.aligned.m8n8.x4.shared.b16 {%0,%1,%2,%3}, [%4];" \
        : "=r"(r0), "=r"(r1), "=r"(r2), "=r"(r3) : "r"(a))

__device__ __forceinline__ void mma_16816(float* c, const uint32_t* a, const uint32_t* b) {
    asm volatile(
        "mma.sync.aligned.m16n8k16.row.col.f32.f16.f16.f32 "
        "{%0,%1,%2,%3}, {%4,%5,%6,%7}, {%8,%9}, {%0,%1,%2,%3};\n"
        : "+f"(c[0]), "+f"(c[1]), "+f"(c[2]), "+f"(c[3])
        : "r"(a[0]), "r"(a[1]), "r"(a[2]), "r"(a[3]), "r"(b[0]), "r"(b[1]));
}

// ============================================================
// Kernel 1 (merged prep): blocks 0..255 = X@L1 partials + fp16(X);
//                         blocks 256..16639 = dequant+transpose W.
// xl1 blocks first so the short dequant blocks fill remaining SMs.
// ============================================================
#define KCHUNK (D_IN / KSPLIT)   // 512
#define XTK 32
#define XROWS 256
#define XL1_BLOCKS (KSPLIT * (NROWS / XROWS))   // 256

__global__ __launch_bounds__(256)
void prep_kernel(const float* __restrict__ X,  const float* __restrict__ L1,
                 const float* __restrict__ w,  const float* __restrict__ c1p,
                 const float* __restrict__ ck) {
    __shared__ __align__(16) char sbuf[XROWS * 33 * 4 + XTK * RANK * 4]; // 35840 B
    const int tid = threadIdx.x;

    if (blockIdx.x >= XL1_BLOCKS) {
        // ---------------- dequant role ----------------
        float (*tile)[33] = (float(*)[33])sbuf;
        const int bid = blockIdx.x - XL1_BLOCKS;
        const float c1 = c1p[0];
        const int n0 = (bid & 127) * 32, k0 = (bid >> 7) * 32;
        const int tx = tid & 31, ty = tid >> 5;
        #pragma unroll
        for (int i = 0; i < 4; i++) {
            int k = k0 + ty + i * 8;
            size_t idx = (size_t)k * D_OUT + n0 + tx;
            tile[ty + i * 8][tx] = (w[idx] * c1) * ck[idx];
        }
        __syncthreads();
        #pragma unroll
        for (int i = 0; i < 4; i++) {
            int n = n0 + ty + i * 8;
            g_Wh[(size_t)n * D_IN + k0 + tx] = __float2half_rn(tile[tx][ty + i * 8]);
        }
        return;
    }

    // ---------------- xl1 role ----------------
    float* xs = (float*)sbuf;                               // [XROWS*33]
    float (*l1s)[RANK] = (float(*)[RANK])(sbuf + XROWS * 33 * 4);
    const int ks   = blockIdx.x & (KSPLIT - 1);
    const int row0 = (blockIdx.x >> 3) * XROWS;
    const int k0   = ks * KCHUNK;

    float acc[RANK];
    #pragma unroll
    for (int r = 0; r < RANK; r++) acc[r] = 0.f;

    for (int t = 0; t < KCHUNK / XTK; t++) {
        const int kt = k0 + t * XTK;
        __syncthreads();
        #pragma unroll
        for (int j = 0; j < 8; j++) {
            int f = tid + j * 256;
            int row = f >> 3, seg = f & 7;
            float4 v = *(const float4*)(X + (size_t)(row0 + row) * D_IN + kt + seg * 4);
            float* xd = xs + row * 33 + seg * 4;
            xd[0] = v.x; xd[1] = v.y; xd[2] = v.z; xd[3] = v.w;
            __half2 h0 = __floats2half2_rn(v.x, v.y);
            __half2 h1 = __floats2half2_rn(v.z, v.w);
            uint2 u = make_uint2(*(uint32_t*)&h0, *(uint32_t*)&h1);
            *(uint2*)(g_Xh + (size_t)(row0 + row) * D_IN + kt + seg * 4) = u;
        }
        if (tid < 128) {
            int kk = tid >> 2, rq = tid & 3;
            *(float4*)&l1s[kk][rq * 4] =
                *(const float4*)(L1 + (size_t)(kt + kk) * RANK + rq * 4);
        }
        __syncthreads();
        const float* xr = xs + tid * 33;
        #pragma unroll
        for (int kk = 0; kk < XTK; kk++) {
            float x = xr[kk];
            float4 a = *(const float4*)&l1s[kk][0];
            float4 b = *(const float4*)&l1s[kk][4];
            float4 c = *(const float4*)&l1s[kk][8];
            float4 d = *(const float4*)&l1s[kk][12];
            acc[0]  += x * a.x; acc[1]  += x * a.y; acc[2]  += x * a.z; acc[3]  += x * a.w;
            acc[4]  += x * b.x; acc[5]  += x * b.y; acc[6]  += x * b.z; acc[7]  += x * b.w;
            acc[8]  += x * c.x; acc[9]  += x * c.y; acc[10] += x * c.z; acc[11] += x * c.w;
            acc[12] += x * d.x; acc[13] += x * d.y; acc[14] += x * d.z; acc[15] += x * d.w;
        }
    }
    float* out = g_Tp + ((size_t)ks * NROWS + row0 + tid) * RANK;
    #pragma unroll
    for (int q = 0; q < 4; q++)
        *(float4*)(out + q * 4) = make_float4(acc[q * 4], acc[q * 4 + 1],
                                              acc[q * 4 + 2], acc[q * 4 + 3]);
}

// ============================================================
// Kernel 2: fp16 mma.sync GEMM, BM=128 BN=128 BK=64,
//           4 warps x (64x64) tiles  -> 25% less smem traffic/FLOP,
//           3-stage mbarrier pipeline, 2 CTAs/SM, fused LoRA epilogue
// ============================================================
#define BM 128
#define BN 128
#define BK 64
#define NTHREADS 128
#define KTILES (D_IN / BK)               // 64
#define A_BYTES (BM * BK * 2)            // 16384
#define B_BYTES (BN * BK * 2)            // 16384
#define STAGE_BYTES (A_BYTES + B_BYTES)  // 32768
#define STAGES 3
#define SMEM_L2   (STAGES * STAGE_BYTES)      // 98304
#define SMEM_TS   (SMEM_L2 + RANK * BN * 4)   // +8192 = 106496
#define SMEM_MBAR (SMEM_TS + BM * RANK * 4)   // +8192 = 114688
#define SMEM_TOT  (SMEM_MBAR + 64)

__global__ __launch_bounds__(NTHREADS, 2)
void gemm_hmma_kernel(float* __restrict__ Y, const float* __restrict__ L2) {
    extern __shared__ __align__(1024) unsigned char smem[];
    const uint32_t sbase = smem_u32(smem);
    const uint32_t mb_full  = sbase + SMEM_MBAR;
    const uint32_t mb_empty = sbase + SMEM_MBAR + 24;
    const int tid = threadIdx.x, warp = tid >> 5, lane = tid & 31;
    const int bN = blockIdx.x, bM = blockIdx.y;
    const int wm = warp & 1, wn = warp >> 1;       // 2 x 2 warps, 64x64 tiles
    const int li = lane & 7, sel = lane >> 3;

    if (tid == 0) {
        #pragma unroll
        for (int s = 0; s < STAGES; s++) {
            mbar_init(mb_full  + s * 8, NTHREADS);
            mbar_init(mb_empty + s * 8, NTHREADS);
        }
    }
    __syncthreads();

    const __half* Ag = g_Xh + (size_t)(bM * BM) * D_IN;
    const __half* Bg = g_Wh + (size_t)(bN * BN) * D_IN;

    auto load_stage = [&](int buf, int kt) {
        const uint32_t ab = sbase + buf * STAGE_BYTES;
        const uint32_t bb = ab + A_BYTES;
        #pragma unroll
        for (int j = 0; j < 8; j++) {          // A: 128 rows x 8 chunks
            int id = tid + j * NTHREADS, r = id >> 3, c = id & 7;
            CP_ASYNC16(ab + r * 128 + (((c ^ (r & 7))) << 4),
                       Ag + (size_t)r * D_IN + kt * BK + c * 8);
        }
        #pragma unroll
        for (int j = 0; j < 8; j++) {          // B: 128 rows x 8 chunks
            int id = tid + j * NTHREADS, r = id >> 3, c = id & 7;
            CP_ASYNC16(bb + r * 128 + (((c ^ (r & 7))) << 4),
                       Bg + (size_t)r * D_IN + kt * BK + c * 8);
        }
        cp_async_arrive_noinc(mb_full + buf * 8);
    };

    load_stage(0, 0);
    load_stage(1, 1);

    // LoRA operand tiles; ts = sum of KSPLIT partials
    float* l2s = (float*)(smem + SMEM_L2);     // [RANK][BN]
    float* ts  = (float*)(smem + SMEM_TS);     // [BM][RANK]
    #pragma unroll
    for (int j = 0; j < 4; j++) {
        int idx = tid + j * NTHREADS, r = idx >> 5, c4 = idx & 31;
        *(float4*)&l2s[r * BN + c4 * 4] =
            *(const float4*)&L2[(size_t)r * D_OUT + bN * BN + c4 * 4];
    }
    #pragma unroll
    for (int j = 0; j < 4; j++) {
        int idx = tid + j * NTHREADS, r = idx >> 2, c4 = idx & 3;
        float4 s = make_float4(0.f, 0.f, 0.f, 0.f);
        #pragma unroll
        for (int ks = 0; ks < KSPLIT; ks++) {
            float4 v = *(const float4*)&g_Tp[(size_t)ks * NROWS * RANK +
                                             (size_t)(bM * BM + r) * RANK + c4 * 4];
            s.x += v.x; s.y += v.y; s.z += v.z; s.w += v.w;
        }
        *(float4*)&ts[r * RANK + c4 * 4] = s;
    }
    __syncthreads();

    float c[4][8][4];
    #pragma unroll
    for (int mt = 0; mt < 4; mt++)
        #pragma unroll
        for (int nt = 0; nt < 8; nt++)
            #pragma unroll
            for (int i = 0; i < 4; i++) c[mt][nt][i] = 0.f;

    const int a_selr = sel & 1, a_selc = sel >> 1;
    const int b_selr = sel >> 1, b_selc = sel & 1;

    for (int kt = 0; kt < KTILES; ++kt) {
        const int tp = kt + 2;
        if (tp < KTILES) {
            const int p = tp % 3;
            if (kt > 0)
                mbar_wait(mb_empty + p * 8, ((tp / 3) - 1) & 1);
            load_stage(p, tp);
        }

        const int s = kt % 3;
        mbar_wait(mb_full + s * 8, (kt / 3) & 1);

        const uint32_t ab = sbase + s * STAGE_BYTES;
        const uint32_t bb = ab + A_BYTES;

        #pragma unroll
        for (int ks = 0; ks < 4; ks++) {
            const int c0 = ks * 2;
            uint32_t a[4][4], b[8][2];
            #pragma unroll
            for (int mt = 0; mt < 4; mt++) {
                int row = wm * 64 + mt * 16 + li + a_selr * 8;
                int ch  = c0 + a_selc;
                LDSM_X4(a[mt][0], a[mt][1], a[mt][2], a[mt][3],
                        ab + row * 128 + (((ch ^ (row & 7))) << 4));
            }
            #pragma unroll
            for (int p = 0; p < 4; p++) {
                int row = wn * 64 + p * 16 + li + b_selr * 8;
                int ch  = c0 + b_selc;
                LDSM_X4(b[p * 2][0], b[p * 2][1], b[p * 2 + 1][0], b[p * 2 + 1][1],
                        bb + row * 128 + (((ch ^ (row & 7))) << 4));
            }
            #pragma unroll
            for (int mt = 0; mt < 4; mt++)
                #pragma unroll
                for (int nt = 0; nt < 8; nt++)
                    mma_16816(c[mt][nt], a[mt], b[nt]);
        }
        mbar_arrive(mb_empty + s * 8);
    }

    // ---------- epilogue: Y = C + T @ L2 ----------
    const int r0 = lane >> 2, cp = (lane & 3) * 2;
    #pragma unroll
    for (int mt = 0; mt < 4; mt++) {
        const int lrA = wm * 64 + mt * 16 + r0;
        const int lrB = lrA + 8;
        float tA[RANK], tB[RANK];
        #pragma unroll
        for (int r = 0; r < RANK; r++) {
            tA[r] = ts[lrA * RANK + r];
            tB[r] = ts[lrB * RANK + r];
        }
        float* yA = Y + (size_t)(bM * BM + lrA) * D_OUT + bN * BN;
        float* yB = Y + (size_t)(bM * BM + lrB) * D_OUT + bN * BN;
        #pragma unroll
        for (int nt = 0; nt < 8; nt++) {
            const int col = wn * 64 + nt * 8 + cp;
            float2 aacc = make_float2(c[mt][nt][0], c[mt][nt][1]);
            float2 bacc = make_float2(c[mt][nt][2], c[mt][nt][3]);
            #pragma unroll
            for (int r = 0; r < RANK; r++) {
                float2 l = *(const float2*)&l2s[r * BN + col];
                aacc.x += tA[r] * l.x; aacc.y += tA[r] * l.y;
                bacc.x += tB[r] * l.x; bacc.y += tB[r] * l.y;
            }
            __stcs((float2*)(yA + col), aacc);
            __stcs((float2*)(yB + col), bacc);
        }
    }
}

// ============================================================
// launch
// ============================================================
extern "C" void kernel_launch(void* const* d_in, const int* in_sizes, int n_in,
                              void* d_out, int out_size) {
    const float* X  = (const float*)d_in[0];
    const float* Wn = (const float*)d_in[1];
    const float* c1 = (const float*)d_in[2];
    const float* ck = (const float*)d_in[3];
    const float* L1 = (const float*)d_in[4];
    const float* L2 = (const float*)d_in[5];
    float* Y = (float*)d_out;

    cudaFuncSetAttribute(gemm_hmma_kernel,
                         cudaFuncAttributeMaxDynamicSharedMemorySize, SMEM_TOT);

    prep_kernel<<<XL1_BLOCKS + (D_OUT / 32) * (D_IN / 32), 256>>>(X, L1, Wn, c1, ck);
    gemm_hmma_kernel<<<dim3(D_OUT / BN, NROWS / BM), NTHREADS, SMEM_TOT>>>(Y, L2);
}

// round 16
// speedup vs baseline: 1.1622x; 1.0251x over previous
#include <cuda_runtime.h>
#include <cuda_fp16.h>
#include <cstdint>

#define D_IN   4096
#define D_OUT  4096
#define NROWS  8192
#define RANK   16

// ---------------- scratch ----------------
__device__ __align__(1024) __half g_Wh[D_OUT * D_IN];  // W^T [N][K], fp16
__device__ __align__(1024) __half g_Xh[NROWS * D_IN];  // X, fp16
#define KSPLIT 8
__device__ __align__(16)   float  g_Tp[KSPLIT * NROWS * RANK]; // X@L1 partials

// ---------------- helpers ----------------
__device__ __forceinline__ uint32_t smem_u32(const void* p) {
    return (uint32_t)__cvta_generic_to_shared(p);
}
#define CP_ASYNC16(dst, src) \
    asm volatile("cp.async.cg.shared.global [%0], [%1], 16;\n" :: "r"(dst), "l"(src))

__device__ __forceinline__ void mbar_init(uint32_t a, uint32_t cnt) {
    asm volatile("mbarrier.init.shared.b64 [%0], %1;" :: "r"(a), "r"(cnt) : "memory");
}
__device__ __forceinline__ void mbar_arrive(uint32_t a) {
    asm volatile("mbarrier.arrive.shared.b64 _, [%0];" :: "r"(a) : "memory");
}
__device__ __forceinline__ void cp_async_arrive_noinc(uint32_t a) {
    asm volatile("cp.async.mbarrier.arrive.noinc.shared.b64 [%0];" :: "r"(a) : "memory");
}
__device__ __forceinline__ void mbar_wait(uint32_t a, uint32_t parity) {
    asm volatile(
        "{\n\t.reg .pred P;\n\t"
        "W%=:\n\t"
        "mbarrier.try_wait.parity.acquire.cta.shared::cta.b64 P, [%0], %1, 0x989680;\n\t"
        "@P bra D%=;\n\t"
        "bra W%=;\n\t"
        "D%=:\n\t}"
        :: "r"(a), "r"(parity) : "memory");
}

#define LDSM_X4(r0, r1, r2, r3, a) \
    asm volatile("ldmatrix.sync.aligned.m8n8.x4.shared.b16 {%0,%1,%2,%3}, [%4];" \
        : "=r"(r0), "=r"(r1), "=r"(r2), "=r"(r3) : "r"(a))

__device__ __forceinline__ void mma_16816(float* c, const uint32_t* a, const uint32_t* b) {
    asm volatile(
        "mma.sync.aligned.m16n8k16.row.col.f32.f16.f16.f32 "
        "{%0,%1,%2,%3}, {%4,%5,%6,%7}, {%8,%9}, {%0,%1,%2,%3};\n"
        : "+f"(c[0]), "+f"(c[1]), "+f"(c[2]), "+f"(c[3])
        : "r"(a[0]), "r"(a[1]), "r"(a[2]), "r"(a[3]), "r"(b[0]), "r"(b[1]));
}

// ============================================================
// Kernel 1 (merged prep): blocks 0..255 = X@L1 partials + fp16(X);
//                         blocks 256..16639 = dequant+transpose W.
// ============================================================
#define KCHUNK (D_IN / KSPLIT)   // 512
#define XTK 32
#define XROWS 256
#define XL1_BLOCKS (KSPLIT * (NROWS / XROWS))   // 256

__global__ __launch_bounds__(256)
void prep_kernel(const float* __restrict__ X,  const float* __restrict__ L1,
                 const float* __restrict__ w,  const float* __restrict__ c1p,
                 const float* __restrict__ ck) {
    __shared__ __align__(16) char sbuf[XROWS * 33 * 4 + XTK * RANK * 4];
    const int tid = threadIdx.x;

    if (blockIdx.x >= XL1_BLOCKS) {
        // ---------------- dequant role ----------------
        float (*tile)[33] = (float(*)[33])sbuf;
        const int bid = blockIdx.x - XL1_BLOCKS;
        const float c1 = c1p[0];
        const int n0 = (bid & 127) * 32, k0 = (bid >> 7) * 32;
        const int tx = tid & 31, ty = tid >> 5;
        #pragma unroll
        for (int i = 0; i < 4; i++) {
            int k = k0 + ty + i * 8;
            size_t idx = (size_t)k * D_OUT + n0 + tx;
            tile[ty + i * 8][tx] = (w[idx] * c1) * ck[idx];
        }
        __syncthreads();
        #pragma unroll
        for (int i = 0; i < 4; i++) {
            int n = n0 + ty + i * 8;
            g_Wh[(size_t)n * D_IN + k0 + tx] = __float2half_rn(tile[tx][ty + i * 8]);
        }
        return;
    }

    // ---------------- xl1 role ----------------
    float* xs = (float*)sbuf;
    float (*l1s)[RANK] = (float(*)[RANK])(sbuf + XROWS * 33 * 4);
    const int ks   = blockIdx.x & (KSPLIT - 1);
    const int row0 = (blockIdx.x >> 3) * XROWS;
    const int k0   = ks * KCHUNK;

    float acc[RANK];
    #pragma unroll
    for (int r = 0; r < RANK; r++) acc[r] = 0.f;

    for (int t = 0; t < KCHUNK / XTK; t++) {
        const int kt = k0 + t * XTK;
        __syncthreads();
        #pragma unroll
        for (int j = 0; j < 8; j++) {
            int f = tid + j * 256;
            int row = f >> 3, seg = f & 7;
            float4 v = *(const float4*)(X + (size_t)(row0 + row) * D_IN + kt + seg * 4);
            float* xd = xs + row * 33 + seg * 4;
            xd[0] = v.x; xd[1] = v.y; xd[2] = v.z; xd[3] = v.w;
            __half2 h0 = __floats2half2_rn(v.x, v.y);
            __half2 h1 = __floats2half2_rn(v.z, v.w);
            uint2 u = make_uint2(*(uint32_t*)&h0, *(uint32_t*)&h1);
            *(uint2*)(g_Xh + (size_t)(row0 + row) * D_IN + kt + seg * 4) = u;
        }
        if (tid < 128) {
            int kk = tid >> 2, rq = tid & 3;
            *(float4*)&l1s[kk][rq * 4] =
                *(const float4*)(L1 + (size_t)(kt + kk) * RANK + rq * 4);
        }
        __syncthreads();
        const float* xr = xs + tid * 33;
        #pragma unroll
        for (int kk = 0; kk < XTK; kk++) {
            float x = xr[kk];
            float4 a = *(const float4*)&l1s[kk][0];
            float4 b = *(const float4*)&l1s[kk][4];
            float4 c = *(const float4*)&l1s[kk][8];
            float4 d = *(const float4*)&l1s[kk][12];
            acc[0]  += x * a.x; acc[1]  += x * a.y; acc[2]  += x * a.z; acc[3]  += x * a.w;
            acc[4]  += x * b.x; acc[5]  += x * b.y; acc[6]  += x * b.z; acc[7]  += x * b.w;
            acc[8]  += x * c.x; acc[9]  += x * c.y; acc[10] += x * c.z; acc[11] += x * c.w;
            acc[12] += x * d.x; acc[13] += x * d.y; acc[14] += x * d.z; acc[15] += x * d.w;
        }
    }
    float* out = g_Tp + ((size_t)ks * NROWS + row0 + tid) * RANK;
    #pragma unroll
    for (int q = 0; q < 4; q++)
        *(float4*)(out + q * 4) = make_float4(acc[q * 4], acc[q * 4 + 1],
                                              acc[q * 4 + 2], acc[q * 4 + 3]);
}

// ============================================================
// Kernel 2: fp16 mma.sync GEMM, BM=128 BN=128 BK=64,
//           4 warps x (64x64), 2-STAGE mbarrier pipeline,
//           82KB smem/CTA -> 2 CTAs/SM, fused LoRA epilogue
// ============================================================
#define BM 128
#define BN 128
#define BK 64
#define NTHREADS 128
#define KTILES (D_IN / BK)               // 64
#define A_BYTES (BM * BK * 2)            // 16384
#define B_BYTES (BN * BK * 2)            // 16384
#define STAGE_BYTES (A_BYTES + B_BYTES)  // 32768
#define STAGES 2
#define SMEM_L2   (STAGES * STAGE_BYTES)      // 65536
#define SMEM_TS   (SMEM_L2 + RANK * BN * 4)   // +8192 = 73728
#define SMEM_MBAR (SMEM_TS + BM * RANK * 4)   // +8192 = 81920
#define SMEM_TOT  (SMEM_MBAR + 64)            // 81984 -> 2 CTAs/SM

__global__ __launch_bounds__(NTHREADS, 2)
void gemm_hmma_kernel(float* __restrict__ Y, const float* __restrict__ L2) {
    extern __shared__ __align__(1024) unsigned char smem[];
    const uint32_t sbase = smem_u32(smem);
    const uint32_t mb_full  = sbase + SMEM_MBAR;        // 2 x 8B
    const uint32_t mb_empty = sbase + SMEM_MBAR + 16;   // 2 x 8B
    const int tid = threadIdx.x, warp = tid >> 5, lane = tid & 31;
    const int bN = blockIdx.x, bM = blockIdx.y;
    const int wm = warp & 1, wn = warp >> 1;       // 2 x 2 warps, 64x64 tiles
    const int li = lane & 7, sel = lane >> 3;

    if (tid == 0) {
        #pragma unroll
        for (int s = 0; s < STAGES; s++) {
            mbar_init(mb_full  + s * 8, NTHREADS);
            mbar_init(mb_empty + s * 8, NTHREADS);
        }
    }
    __syncthreads();

    const __half* Ag = g_Xh + (size_t)(bM * BM) * D_IN;
    const __half* Bg = g_Wh + (size_t)(bN * BN) * D_IN;

    auto load_stage = [&](int buf, int kt) {
        const uint32_t ab = sbase + buf * STAGE_BYTES;
        const uint32_t bb = ab + A_BYTES;
        #pragma unroll
        for (int j = 0; j < 8; j++) {          // A: 128 rows x 8 chunks
            int id = tid + j * NTHREADS, r = id >> 3, c = id & 7;
            CP_ASYNC16(ab + r * 128 + (((c ^ (r & 7))) << 4),
                       Ag + (size_t)r * D_IN + kt * BK + c * 8);
        }
        #pragma unroll
        for (int j = 0; j < 8; j++) {          // B: 128 rows x 8 chunks
            int id = tid + j * NTHREADS, r = id >> 3, c = id & 7;
            CP_ASYNC16(bb + r * 128 + (((c ^ (r & 7))) << 4),
                       Bg + (size_t)r * D_IN + kt * BK + c * 8);
        }
        cp_async_arrive_noinc(mb_full + buf * 8);
    };

    load_stage(0, 0);

    // LoRA operand tiles; ts = sum of KSPLIT partials
    float* l2s = (float*)(smem + SMEM_L2);     // [RANK][BN]
    float* ts  = (float*)(smem + SMEM_TS);     // [BM][RANK]
    #pragma unroll
    for (int j = 0; j < 4; j++) {
        int idx = tid + j * NTHREADS, r = idx >> 5, c4 = idx & 31;
        *(float4*)&l2s[r * BN + c4 * 4] =
            *(const float4*)&L2[(size_t)r * D_OUT + bN * BN + c4 * 4];
    }
    #pragma unroll
    for (int j = 0; j < 4; j++) {
        int idx = tid + j * NTHREADS, r = idx >> 2, c4 = idx & 3;
        float4 s = make_float4(0.f, 0.f, 0.f, 0.f);
        #pragma unroll
        for (int ks = 0; ks < KSPLIT; ks++) {
            float4 v = *(const float4*)&g_Tp[(size_t)ks * NROWS * RANK +
                                             (size_t)(bM * BM + r) * RANK + c4 * 4];
            s.x += v.x; s.y += v.y; s.z += v.z; s.w += v.w;
        }
        *(float4*)&ts[r * RANK + c4 * 4] = s;
    }
    __syncthreads();

    float c[4][8][4];
    #pragma unroll
    for (int mt = 0; mt < 4; mt++)
        #pragma unroll
        for (int nt = 0; nt < 8; nt++)
            #pragma unroll
            for (int i = 0; i < 4; i++) c[mt][nt][i] = 0.f;

    const int a_selr = sel & 1, a_selc = sel >> 1;
    const int b_selr = sel >> 1, b_selc = sel & 1;

    for (int kt = 0; kt < KTILES; ++kt) {
        // produce tile kt+1 into stage (kt+1)%2
        const int tp = kt + 1;
        if (tp < KTILES) {
            const int p = tp & 1;
            if (kt > 0)                                  // tp>=2: stage reused
                mbar_wait(mb_empty + p * 8, ((tp >> 1) - 1) & 1);
            load_stage(p, tp);
        }

        // consume tile kt from stage kt%2
        const int s = kt & 1;
        mbar_wait(mb_full + s * 8, (kt >> 1) & 1);

        const uint32_t ab = sbase + s * STAGE_BYTES;
        const uint32_t bb = ab + A_BYTES;

        #pragma unroll
        for (int ks = 0; ks < 4; ks++) {
            const int c0 = ks * 2;
            uint32_t a[4][4], b[8][2];
            #pragma unroll
            for (int mt = 0; mt < 4; mt++) {
                int row = wm * 64 + mt * 16 + li + a_selr * 8;
                int ch  = c0 + a_selc;
                LDSM_X4(a[mt][0], a[mt][1], a[mt][2], a[mt][3],
                        ab + row * 128 + (((ch ^ (row & 7))) << 4));
            }
            #pragma unroll
            for (int p = 0; p < 4; p++) {
                int row = wn * 64 + p * 16 + li + b_selr * 8;
                int ch  = c0 + b_selc;
                LDSM_X4(b[p * 2][0], b[p * 2][1], b[p * 2 + 1][0], b[p * 2 + 1][1],
                        bb + row * 128 + (((ch ^ (row & 7))) << 4));
            }
            #pragma unroll
            for (int mt = 0; mt < 4; mt++)
                #pragma unroll
                for (int nt = 0; nt < 8; nt++)
                    mma_16816(c[mt][nt], a[mt], b[nt]);
        }
        mbar_arrive(mb_empty + s * 8);
    }

    // ---------- epilogue: Y = C + T @ L2 ----------
    const int r0 = lane >> 2, cp = (lane & 3) * 2;
    #pragma unroll
    for (int mt = 0; mt < 4; mt++) {
        const int lrA = wm * 64 + mt * 16 + r0;
        const int lrB = lrA + 8;
        float tA[RANK], tB[RANK];
        #pragma unroll
        for (int r = 0; r < RANK; r++) {
            tA[r] = ts[lrA * RANK + r];
            tB[r] = ts[lrB * RANK + r];
        }
        float* yA = Y + (size_t)(bM * BM + lrA) * D_OUT + bN * BN;
        float* yB = Y + (size_t)(bM * BM + lrB) * D_OUT + bN * BN;
        #pragma unroll
        for (int nt = 0; nt < 8; nt++) {
            const int col = wn * 64 + nt * 8 + cp;
            float2 aacc = make_float2(c[mt][nt][0], c[mt][nt][1]);
            float2 bacc = make_float2(c[mt][nt][2], c[mt][nt][3]);
            #pragma unroll
            for (int r = 0; r < RANK; r++) {
                float2 l = *(const float2*)&l2s[r * BN + col];
                aacc.x += tA[r] * l.x; aacc.y += tA[r] * l.y;
                bacc.x += tB[r] * l.x; bacc.y += tB[r] * l.y;
            }
            __stcs((float2*)(yA + col), aacc);
            __stcs((float2*)(yB + col), bacc);
        }
    }
}

// ============================================================
// launch
// ============================================================
extern "C" void kernel_launch(void* const* d_in, const int* in_sizes, int n_in,
                              void* d_out, int out_size) {
    const float* X  = (const float*)d_in[0];
    const float* Wn = (const float*)d_in[1];
    const float* c1 = (const float*)d_in[2];
    const float* ck = (const float*)d_in[3];
    const float* L1 = (const float*)d_in[4];
    const float* L2 = (const float*)d_in[5];
    float* Y = (float*)d_out;

    cudaFuncSetAttribute(gemm_hmma_kernel,
                         cudaFuncAttributeMaxDynamicSharedMemorySize, SMEM_TOT);

    prep_kernel<<<XL1_BLOCKS + (D_OUT / 32) * (D_IN / 32), 256>>>(X, L1, Wn, c1, ck);
    gemm_hmma_kernel<<<dim3(D_OUT / BN, NROWS / BM), NTHREADS, SMEM_TOT>>>(Y, L2);
}